// round 3
// baseline (speedup 1.0000x reference)
#include <cuda_runtime.h>

// DerivativeDILATEloss: soft-DTW(gamma=0.01) over D[i,j] = (dy[i]-dx[j])^2.
// B=64 batches, N=512 -> n=511. Output: mean over batch (ALPHA=1).
//
// Round 3 (= Round 2 + compile fix): each batch split across 2 CTAs
// (rows 1..256 / 257..511), pipelined via global-memory boundary publication
// (groups of 8 + monotone flag). Softmin computed in a scaled domain
// (k = 100/ln2) so it is pure ex2/lg2 with no multiplies; dx/dy pre-scaled
// by sqrt(k).

#define NSEQ   511
#define NBATCH 64
#define INFV   1.0e9f
#define INVK   0.0069314718055994531f  // ln(2)/100
#define SQRTK  12.011224298677374f     // sqrt(100/ln 2)

__device__ __forceinline__ float ex2f(float x) {
    float r;
    asm("ex2.approx.f32 %0, %1;" : "=f"(r) : "f"(x));
    return r;
}
__device__ __forceinline__ float lg2f(float x) {
    float r;
    asm("lg2.approx.f32 %0, %1;" : "=f"(r) : "f"(x));
    return r;
}

__device__ float g_bnd[NBATCH][512];   // scaled R[256, j], stored at [j-1]
__device__ int   g_flag[NBATCH];       // highest published column (monotone)
__device__ float g_partial[NBATCH];

__global__ __launch_bounds__(256, 1)
void sdtw_kernel(const float* __restrict__ input,
                 const float* __restrict__ target)
{
    __shared__ float sdx[NSEQ + 1];
    __shared__ float sdy[NSEQ + 1];
    __shared__ float buf[3][257];

    const int b     = blockIdx.x >> 1;
    const int roleB = blockIdx.x & 1;
    const int t     = threadIdx.x;

    const float* in_b = input  + b * (NSEQ + 1);
    const float* tg_b = target + b * (NSEQ + 1);

    // first differences, pre-scaled by sqrt(k)
    for (int idx = t; idx < NSEQ; idx += 256) {
        sdx[idx] = (in_b[idx + 1] - in_b[idx]) * SQRTK;
        sdy[idx] = (tg_b[idx + 1] - tg_b[idx]) * SQRTK;
    }
    if (t == 0) { sdx[NSEQ] = 0.0f; sdy[NSEQ] = 0.0f; }

    // init rotating diagonal buffers (indices 0..256)
    buf[0][t] = INFV;  buf[1][t] = INFV;
    if (t == 0) { buf[0][256] = INFV; buf[1][256] = INFV; buf[2][256] = INFV; }

    if (!roleB) {
        // ---------------- CTA A: rows 1..256 ----------------
        if (t == 0) buf[0][0] = 0.0f;   // R[0,0] = 0 on diag 0
        __syncthreads();

        const int   i   = t + 1;            // 1..256
        const float dyr = sdy[i - 1];
        float *r2 = buf[0], *r1 = buf[1], *rc = buf[2];

        for (int d = 2; d <= 767; ++d) {
            const int  j     = d - i;
            const bool valid = (j >= 1) & (j <= NSEQ);
            const int  jc    = min(max(j - 1, 0), NSEQ - 1);

            const float a = r2[t];
            const float e = r1[t];
            const float c = r1[t + 1];
            const float m = fminf(a, fminf(e, c));
            const float s = ex2f(m - a) + ex2f(m - e) + ex2f(m - c);
            const float smin = m - lg2f(s);
            const float dv   = dyr - sdx[jc];
            const float val  = valid ? fmaf(dv, dv, smin) : INFV;

            rc[t + 1] = val;
            if (t == 0) rc[0] = INFV;         // R[0, d] = INF for d >= 2

            if (t == 255) {                   // row 256: publish boundary
                if (valid) {
                    g_bnd[b][j - 1] = val;
                    if (((j & 7) == 0) || (j == NSEQ)) {
                        __threadfence();
                        *((volatile int*)&g_flag[b]) = j;
                    }
                }
            }
            __syncthreads();
            float* tmp = r2; r2 = r1; r1 = rc; rc = tmp;
        }
    } else {
        // ---------------- CTA B: rows 257..511 ----------------
        const int   i   = 257 + t;                        // t=0..254 valid
        const float dyr = sdy[min(i - 1, NSEQ - 1)];
        float *r2 = buf[0], *r1 = buf[1], *rc = buf[2];

        float ring[16];                                   // boundary cols cache
        float bnd1 = INFV, bnd2 = INFV;

        if (t == 0) {
            // preload boundary columns 1..16
            while (*((volatile int*)&g_flag[b]) < 16) { }
            __threadfence();
            #pragma unroll
            for (int q = 0; q < 16; ++q) ring[q] = g_bnd[b][q];
            bnd1 = ring[0];                               // R[256, 1]
        }
        __syncthreads();

        for (int d = 258; d <= 1022; ++d) {
            const int  j     = d - i;
            const bool valid = (j >= 1) & (j <= NSEQ) & (i <= NSEQ);
            const int  jc    = min(max(j - 1, 0), NSEQ - 1);

            const float a = (t == 0) ? bnd2 : r2[t];
            const float e = (t == 0) ? bnd1 : r1[t];
            const float c = r1[t + 1];
            const float m = fminf(a, fminf(e, c));
            const float s = ex2f(m - a) + ex2f(m - e) + ex2f(m - c);
            const float smin = m - lg2f(s);
            const float dv   = dyr - sdx[jc];
            const float val  = valid ? fmaf(dv, dv, smin) : INFV;

            rc[t + 1] = val;

            if (t == 0) {
                const int cb = d - 256;       // column that becomes bnd1
                bnd2 = bnd1;
                // refill one group (8 cols) ahead of consumption
                if (((cb & 7) == 1) && (cb + 8 <= NSEQ)) {
                    const int need = min(cb + 15, NSEQ);
                    while (*((volatile int*)&g_flag[b]) < need) { }
                    __threadfence();
                    const int base = cb + 7;  // gbuf index of col cb+8
                    #pragma unroll
                    for (int q = 0; q < 8; ++q)
                        ring[(base + q) & 15] = g_bnd[b][base + q];
                }
                bnd1 = (cb >= 1 && cb <= NSEQ) ? ring[(cb - 1) & 15] : INFV;
            }
            __syncthreads();
            float* tmp = r2; r2 = r1; r1 = rc; rc = tmp;
        }

        // final diagonal (d=1022) is now in r1; R[511,511] at index 255
        if (t == 254) g_partial[b] = r1[255] * INVK;
    }
}

__global__ void reduce_kernel(float* __restrict__ out)
{
    const int l = threadIdx.x;
    float s = g_partial[l] + g_partial[l + 32];
    #pragma unroll
    for (int o = 16; o > 0; o >>= 1)
        s += __shfl_down_sync(0xFFFFFFFFu, s, o);
    if (l == 0) out[0] = s * (1.0f / (float)NBATCH);
}

extern "C" void kernel_launch(void* const* d_in, const int* in_sizes, int n_in,
                              void* d_out, int out_size)
{
    const float* input  = (const float*)d_in[0];
    const float* target = (const float*)d_in[1];
    float* out = (float*)d_out;

    sdtw_kernel<<<2 * NBATCH, 256>>>(input, target);
    reduce_kernel<<<1, 32>>>(out);
}

// round 4
// speedup vs baseline: 1.2301x; 1.2301x over previous
#include <cuda_runtime.h>

// DerivativeDILATEloss: soft-DTW(gamma=0.01) over D[i,j] = (dy[i]-dx[j])^2.
// B=64, N=512 -> n=511. Output: mean over batch (ALPHA=1).
//
// Round 4: warp-synchronous register wavefront. One CTA per batch, 512
// threads (thread k = matrix row k; k=0 is the row-0 boundary). Diagonals
// live in registers; intra-warp neighbor via shfl_up; inter-warp boundary
// via tagged smem mailbox rings (spin-poll, NO __syncthreads in the loop).
// Scaled domain (k = 100/ln2): softmin = m - lg2(1 + ex2(m-mid) + ex2(m-hi))
// -- only 3 MUFU ops per cell.

#define NSEQ   511
#define NBATCH 64
#define INFV   1.0e9f
#define INVK   0.0069314718055994531f  // ln(2)/100
#define SQRTK  12.011224298677374f     // sqrt(100/ln2)
#define RING   64

__device__ __forceinline__ float ex2f(float x) {
    float r; asm("ex2.approx.f32 %0, %1;" : "=f"(r) : "f"(x)); return r;
}
__device__ __forceinline__ float lg2f(float x) {
    float r; asm("lg2.approx.f32 %0, %1;" : "=f"(r) : "f"(x)); return r;
}

__device__ float g_partial[NBATCH];

__global__ __launch_bounds__(512, 1)
void sdtw_kernel(const float* __restrict__ input,
                 const float* __restrict__ target)
{
    __shared__ float sdxp[1536];                  // padded dx, logical base 512
    __shared__ unsigned long long mbox[15][RING]; // warp w publishes in mbox[w]
    __shared__ int prog[16];                      // consumer progress per warp

    const int b    = blockIdx.x;
    const int t    = threadIdx.x;      // row index k
    const int w    = t >> 5;
    const int lane = t & 31;

    const float* in_b = input  + b * (NSEQ + 1);
    const float* tg_b = target + b * (NSEQ + 1);

    // dx padded so sdxp[512 + (d - t - 1)] is always in bounds (d:2..1022)
    #pragma unroll
    for (int rep = 0; rep < 3; ++rep) {
        int idx = t + rep * 512;
        float v = 0.0f;
        int q = idx - 512;
        if (q >= 0 && q < NSEQ) v = (in_b[q + 1] - in_b[q]) * SQRTK;
        sdxp[idx] = v;
    }
    const float dyr = (t >= 1) ? (tg_b[t] - tg_b[t - 1]) * SQRTK : 0.0f;

    // init mailboxes (tag = -1 never matches d in [2,1022]) and progress
    for (int idx = t; idx < 15 * RING; idx += 512)
        ((unsigned long long*)mbox)[idx] = 0xFFFFFFFF00000000ull;
    if (t < 16) prog[t] = 1;
    __syncthreads();   // only barrier: inputs + mailboxes ready

    // diag registers: r1 = R[t, (d-1)-t]; r2u = R[t-1, (d-2)-(t-1)]
    float r1   = INFV;                       // diag 1: all INF
    float r2u  = (t == 1) ? 0.0f : INFV;     // diag 0: R[0,0] = 0
    float bnd1 = INFV;                       // lane-0 substitute for shfl
    const int d_lo = (t >= 1) ? (t + 1) : 4000;   // valid window [d_lo, d_lo+510]
    int pp = 1;                              // producer's view of consumer progress

    #pragma unroll 2
    for (int d = 2; d <= 2 * NSEQ; ++d) {
        float r1u = __shfl_up_sync(0xFFFFFFFFu, r1, 1);
        if (lane == 0) r1u = bnd1;

        // softmin over (a,e,c): min element contributes ex2(0)=1 exactly
        const float a = r2u, e = r1u, c = r1;
        const float mn0 = fminf(a, e), mx0 = fmaxf(a, e);
        const float m   = fminf(mn0, c);
        const float mid = fminf(mx0, fmaxf(mn0, c));
        const float hi  = fmaxf(mx0, c);
        const float s   = 1.0f + ex2f(m - mid) + ex2f(m - hi);
        const float smin = m - lg2f(s);

        const float dxv = sdxp[512 + d - t - 1];
        const float dv  = dyr - dxv;
        const bool valid = ((unsigned)(d - d_lo) <= 510u);
        const float val  = valid ? fmaf(dv, dv, smin) : INFV;

        r2u = r1u;        // rotate: this step's r1[k-1] is next step's r2[k-1]
        r1  = val;

        // producer: publish lane-31's new diag-d value to warp w+1
        if (w < 15) {
            if (d - pp > RING - 16) {   // backpressure (rarely taken)
                do { pp = ((volatile int*)prog)[w + 1]; } while (d - pp > RING - 16);
            }
            if (lane == 31) {
                unsigned long long pkt =
                    ((unsigned long long)(unsigned)d << 32) | __float_as_uint(val);
                *((volatile unsigned long long*)&mbox[w][d & (RING - 1)]) = pkt;
            }
        }

        // consumer: fetch below-warp's diag-d boundary for next step
        if (w >= 1) {
            unsigned long long v;
            do {
                v = *((volatile unsigned long long*)&mbox[w - 1][d & (RING - 1)]);
            } while ((int)(v >> 32) != d);
            bnd1 = __uint_as_float((unsigned)v);
            if (((d & 7) == 0) && lane == 0) ((volatile int*)prog)[w] = d;
        }
    }

    // after step d=1022, r1 of thread 511 = R[511,511] (scaled)
    if (t == NSEQ) g_partial[b] = r1 * INVK;
}

__global__ void reduce_kernel(float* __restrict__ out)
{
    const int l = threadIdx.x;
    float s = g_partial[l] + g_partial[l + 32];
    #pragma unroll
    for (int o = 16; o > 0; o >>= 1)
        s += __shfl_down_sync(0xFFFFFFFFu, s, o);
    if (l == 0) out[0] = s * (1.0f / (float)NBATCH);
}

extern "C" void kernel_launch(void* const* d_in, const int* in_sizes, int n_in,
                              void* d_out, int out_size)
{
    const float* input  = (const float*)d_in[0];
    const float* target = (const float*)d_in[1];
    float* out = (float*)d_out;

    sdtw_kernel<<<NBATCH, 512>>>(input, target);
    reduce_kernel<<<1, 32>>>(out);
}

// round 5
// speedup vs baseline: 1.7084x; 1.3888x over previous
#include <cuda_runtime.h>

// DerivativeDILATEloss: soft-DTW(gamma=0.01), D[i,j]=(dy_i-dx_j)^2, B=64, n=511.
//
// Round 5: free-running warp wavefront. Thread t = row t; diagonals in
// registers; intra-warp neighbor via shfl_up; inter-warp boundary via
// FULL-LENGTH per-warp smem buffers (no ring, no backpressure -> lower warps
// run ahead, consumer polls hit on first try). R carried as (m,s) pair with
// value = m - log2(s): recurrence uses only 3 ex2 per cell, NO lg2.
// Exact power-of-2 renorm of s every 4 steps. Scaled domain k=100/ln2.

#define NSEQ   511
#define NBATCH 64
#define INFV   1.0e9f
#define INVK   0.0069314718055994531f  // ln(2)/100
#define SQRTK  12.011224298677374f     // sqrt(100/ln2)

// dyn smem: sdxp 1536*4 | cnt 16*4 | bbuf 15*1024*8
#define SMEM_BYTES (6144 + 64 + 15*1024*8)

__device__ __forceinline__ float ex2f(float x){float r;asm("ex2.approx.f32 %0,%1;":"=f"(r):"f"(x));return r;}
__device__ __forceinline__ float lg2f(float x){float r;asm("lg2.approx.f32 %0,%1;":"=f"(r):"f"(x));return r;}
__device__ __forceinline__ void st_rel(int* p, int v){
    unsigned a=(unsigned)__cvta_generic_to_shared(p);
    asm volatile("st.release.cta.shared.b32 [%0],%1;"::"r"(a),"r"(v):"memory");
}
__device__ __forceinline__ int ld_acq(const int* p){
    unsigned a=(unsigned)__cvta_generic_to_shared((void*)p); int v;
    asm volatile("ld.acquire.cta.shared.b32 %0,[%1];":"=r"(v):"r"(a):"memory");
    return v;
}

__device__ float g_partial[NBATCH];

__global__ __launch_bounds__(512, 1)
void sdtw_kernel(const float* __restrict__ input,
                 const float* __restrict__ target)
{
    extern __shared__ char smem_raw[];
    float*  sdxp = (float*)smem_raw;              // padded dx, base 512
    int*    cnt  = (int*)(smem_raw + 6144);       // per-warp progress
    float2* bbuf = (float2*)(smem_raw + 6208);    // boundary (m,s) pairs

    const int b    = blockIdx.x;
    const int t    = threadIdx.x;       // row index
    const int w    = t >> 5;
    const int lane = t & 31;

    const float* in_b = input  + b * (NSEQ + 1);
    const float* tg_b = target + b * (NSEQ + 1);

    #pragma unroll
    for (int rep = 0; rep < 3; ++rep) {
        int idx = t + rep * 512;
        float v = 0.0f;
        int q = idx - 512;
        if (q >= 0 && q < NSEQ) v = (in_b[q + 1] - in_b[q]) * SQRTK;
        sdxp[idx] = v;
    }
    if (t < 16) cnt[t] = 0;
    const float dyr = (t >= 1) ? (tg_b[t] - tg_b[t - 1]) * SQRTK : 0.0f;
    __syncthreads();   // only CTA-wide barrier

    // (m,s): value = m - log2(s).  r1 = own diag d-1, r2u = upper diag d-2.
    float r1m  = INFV, r1s = 1.0f;
    float r2um = (t == 1) ? 0.0f : INFV, r2us = 1.0f;
    float bcm  = INFV, bcs = 1.0f;       // lane-0 boundary (diag d-1)
    int   cc   = 0;                       // cached producer counter
    const int dlo = (t >= 1) ? (t + 1) : 4000;
    const float* dxp = sdxp + 512 - t - 1;          // dxp[d] = dx[j-1] scaled

    float2*       pub = bbuf + w * 1024;            // used when w < 15
    const float2* sub = bbuf + (w - 1) * 1024;      // used when w >= 1

    #pragma unroll 4
    for (int d = 2; d <= 2 * NSEQ; ++d) {
        // prefetch next boundary pair (consumed next iteration)
        float2 bn;
        if (w >= 1) {
            if (cc < d) { do { cc = ld_acq(&cnt[w - 1]); } while (cc < d); }
            bn = sub[d];
        }

        float r1um = __shfl_up_sync(0xFFFFFFFFu, r1m, 1);
        float r1us = __shfl_up_sync(0xFFFFFFFFu, r1s, 1);
        if (lane == 0) { r1um = bcm; r1us = bcs; }

        // softmin in (m,s) form: m* = min m_k ; s = sum s_k * 2^(m*-m_k)
        const float mm = fminf(fminf(r2um, r1um), r1m);
        float s_new = r2us * ex2f(mm - r2um)
                    + r1us * ex2f(mm - r1um)
                    + r1s  * ex2f(mm - r1m);
        const float dv = dyr - dxp[d];
        float m_new = fmaf(dv, dv, mm);

        const bool valid = ((unsigned)(d - dlo) <= 510u);
        if (!valid) { m_new = INFV; s_new = 1.0f; }

        if ((d & 3) == 0) {   // exact power-of-2 renorm: fold exponent into m
            unsigned sb = __float_as_uint(s_new);
            int e = (int)(sb >> 23) - 127;
            s_new = __uint_as_float((sb & 0x007FFFFFu) | 0x3F800000u);
            m_new -= (float)e;
        }

        r2um = r1um; r2us = r1us;
        r1m  = m_new; r1s = s_new;

        if (w < 15 && lane == 31) {
            pub[d] = make_float2(m_new, s_new);
            if ((d & 3) == 0 || d == 2 * NSEQ) st_rel(&cnt[w], d);
        }
        if (w >= 1) { bcm = bn.x; bcs = bn.y; }
    }

    // thread 511 holds R[511,511] as (m,s)
    if (t == NSEQ) g_partial[b] = (r1m - lg2f(r1s)) * INVK;
}

__global__ void reduce_kernel(float* __restrict__ out)
{
    const int l = threadIdx.x;
    float s = g_partial[l] + g_partial[l + 32];
    #pragma unroll
    for (int o = 16; o > 0; o >>= 1)
        s += __shfl_down_sync(0xFFFFFFFFu, s, o);
    if (l == 0) out[0] = s * (1.0f / (float)NBATCH);
}

extern "C" void kernel_launch(void* const* d_in, const int* in_sizes, int n_in,
                              void* d_out, int out_size)
{
    const float* input  = (const float*)d_in[0];
    const float* target = (const float*)d_in[1];
    float* out = (float*)d_out;

    cudaFuncSetAttribute(sdtw_kernel,
                         cudaFuncAttributeMaxDynamicSharedMemorySize, SMEM_BYTES);
    sdtw_kernel<<<NBATCH, 512, SMEM_BYTES>>>(input, target);
    reduce_kernel<<<1, 32>>>(out);
}